// round 10
// baseline (speedup 1.0000x reference)
#include <cuda_runtime.h>
#include <cuda_bf16.h>
#include <cstdint>

#define NB 2
#define NS 2048
#define NHID 2048
#define NHEADS 16
#define HD 128
#define N3 6144
#define M_TOT 4096   // NB*NS

// ---------------- scratch (__device__ globals per allocation rules) --------
__device__ __align__(16) __nv_bfloat16 g_xh[M_TOT*NHID];
__device__ __align__(16) __nv_bfloat16 g_xl[M_TOT*NHID];
__device__ __align__(16) __nv_bfloat16 g_Wqh[N3*NHID];    // Wqkv^T [6144][2048]
__device__ __align__(16) __nv_bfloat16 g_Wql[N3*NHID];
__device__ __align__(16) __nv_bfloat16 g_Woh[NHID*NHID];  // Wo^T [2048][2048]
__device__ __align__(16) __nv_bfloat16 g_Wol[NHID*NHID];
__device__ __align__(16) __nv_bfloat16 g_Oh[M_TOT*NHID];
__device__ __align__(16) __nv_bfloat16 g_Ol[M_TOT*NHID];
// per-head Q/K/V hi/lo: [bh][2048][128]
__device__ __align__(16) __nv_bfloat16 g_Qh[NB*NHEADS*NS*HD];
__device__ __align__(16) __nv_bfloat16 g_Ql[NB*NHEADS*NS*HD];
__device__ __align__(16) __nv_bfloat16 g_Kh[NB*NHEADS*NS*HD];
__device__ __align__(16) __nv_bfloat16 g_Kl[NB*NHEADS*NS*HD];
__device__ __align__(16) __nv_bfloat16 g_Vh[NB*NHEADS*NS*HD];
__device__ __align__(16) __nv_bfloat16 g_Vl[NB*NHEADS*NS*HD];

// ---------------- helpers --------------------------------------------------
__device__ __forceinline__ uint32_t smem_u32(const void* p) {
    uint32_t a;
    asm("{ .reg .u64 t; cvta.to.shared.u64 t, %1; cvt.u32.u64 %0, t; }" : "=r"(a) : "l"(p));
    return a;
}
#define CP_ASYNC16(s, g) asm volatile("cp.async.cg.shared.global [%0], [%1], 16;" :: "r"(s), "l"(g) : "memory")
#define CP_COMMIT()      asm volatile("cp.async.commit_group;" ::: "memory")
#define CP_WAIT(n)       asm volatile("cp.async.wait_group %0;" :: "n"(n) : "memory")

__device__ __forceinline__ void mma_bf16(float* d, const uint32_t* a, uint32_t b0, uint32_t b1) {
    asm volatile(
        "mma.sync.aligned.m16n8k16.row.col.f32.bf16.bf16.f32 "
        "{%0,%1,%2,%3}, {%4,%5,%6,%7}, {%8,%9}, {%0,%1,%2,%3};"
        : "+f"(d[0]), "+f"(d[1]), "+f"(d[2]), "+f"(d[3])
        : "r"(a[0]), "r"(a[1]), "r"(a[2]), "r"(a[3]), "r"(b0), "r"(b1));
}

// ldmatrix x4: matrix i taken from address group lanes 8i..8i+7
__device__ __forceinline__ void ldsm_x4(uint32_t* r, uint32_t addr) {
    asm volatile("ldmatrix.sync.aligned.m8n8.x4.shared.b16 {%0,%1,%2,%3}, [%4];"
        : "=r"(r[0]), "=r"(r[1]), "=r"(r[2]), "=r"(r[3]) : "r"(addr));
}

// pack (x -> low half, y -> high half) as bf16x2 hi + residual lo
__device__ __forceinline__ void pack_hl(float x, float y, uint32_t& h, uint32_t& l) {
    __nv_bfloat162 hh = __floats2bfloat162_rn(x, y);
    float rx = x - __bfloat162float(hh.x);
    float ry = y - __bfloat162float(hh.y);
    __nv_bfloat162 ll = __floats2bfloat162_rn(rx, ry);
    h = *(uint32_t*)&hh;
    l = *(uint32_t*)&ll;
}

// ---------------------------------------------------------------------------
// hi/lo bf16 split kernels
// ---------------------------------------------------------------------------
__global__ __launch_bounds__(256)
void split_x_kernel(const float* __restrict__ src)
{
    size_t i = ((size_t)blockIdx.x * 256 + threadIdx.x) * 4;
    float4 v = *(const float4*)(src + i);
    uint32_t h0, l0, h1, l1;
    pack_hl(v.x, v.y, h0, l0);
    pack_hl(v.z, v.w, h1, l1);
    *(uint32_t*)&g_xh[i]     = h0;
    *(uint32_t*)&g_xh[i + 2] = h1;
    *(uint32_t*)&g_xl[i]     = l0;
    *(uint32_t*)&g_xl[i + 2] = l1;
}

template<int WHICH>  // 0: Wqkv [2048][6144] -> g_Wqh/l [6144][2048]; 1: Wo -> g_Woh/l
__global__ __launch_bounds__(256)
void split_tr_kernel(const float* __restrict__ W)
{
    constexpr int N = (WHICH == 0) ? N3 : NHID;
    __nv_bfloat16* dh = (WHICH == 0) ? g_Wqh : g_Woh;
    __nv_bfloat16* dl = (WHICH == 0) ? g_Wql : g_Wol;
    __shared__ float t[32][33];
    int k0 = blockIdx.y * 32, n0 = blockIdx.x * 32;
    int tx = threadIdx.x, ty = threadIdx.y;
#pragma unroll
    for (int i = 0; i < 4; i++)
        t[ty + i * 8][tx] = W[(size_t)(k0 + ty + i * 8) * N + n0 + tx];
    __syncthreads();
#pragma unroll
    for (int i = 0; i < 4; i++) {
        float v = t[tx][ty + i * 8];
        __nv_bfloat16 h = __float2bfloat16(v);
        size_t o = (size_t)(n0 + ty + i * 8) * NHID + k0 + tx;
        dh[o] = h;
        dl[o] = __float2bfloat16(v - __bfloat162float(h));
    }
}

// ---------------------------------------------------------------------------
// Split-bf16 HMMA GEMM: D[M,N] = A @ B^T + bias   (3-pass error compensation,
// ldmatrix fragment loads, hoisted cross-pass reuse)
// MODE 0: +bqkv, scatter hi/lo bf16 -> g_{Q,K,V}{h,l} ; MODE 1: +bo -> C fp32
// Tiles [128 rows][40 halves] (80 B stride: ldmatrix rows hit 16B-banks 5r%8).
// ---------------------------------------------------------------------------
#define TILE_BYTES_G (128 * 80)
#define GEMM_SMEM (2 * 4 * TILE_BYTES_G)

template<int MODE>
__global__ __launch_bounds__(256, 2)
void gemm_mma(const float* __restrict__ bias, float* __restrict__ C)
{
    constexpr int Kdim = NHID;
    constexpr int NT = Kdim / 32;

    extern __shared__ char smem[];
    const uint32_t sbase = smem_u32(smem);

    const int tid  = threadIdx.x;
    const int wid  = tid >> 5;
    const int lane = tid & 31;
    const int mBase = blockIdx.y * 128;
    const int nBase = blockIdx.x * 128;
    const int wm = (wid >> 2) * 64;
    const int wn = (wid & 3) * 32;

    // ldmatrix per-lane addressing
    const int arow = (lane & 7) + ((lane >> 3) & 1) * 8;  // row within 16-row block
    const int koff = ((lane >> 4) & 1) * 16;              // 16B k-chunk select

    const __nv_bfloat16* Ah = (MODE == 0) ? g_xh : g_Oh;
    const __nv_bfloat16* Al = (MODE == 0) ? g_xl : g_Ol;
    const __nv_bfloat16* Bh = (MODE == 0) ? g_Wqh : g_Woh;
    const __nv_bfloat16* Bl = (MODE == 0) ? g_Wql : g_Wol;

    const __nv_bfloat16* srcs[4] = {
        Ah + (size_t)mBase * Kdim, Al + (size_t)mBase * Kdim,
        Bh + (size_t)nBase * Kdim, Bl + (size_t)nBase * Kdim };

    float acc[4][4][4];
#pragma unroll
    for (int i = 0; i < 4; i++)
#pragma unroll
        for (int j = 0; j < 4; j++)
#pragma unroll
            for (int q = 0; q < 4; q++) acc[i][j][q] = 0.f;

    auto load_stage = [&](int t, int stage) {
        const int k0 = t * 32;
#pragma unroll
        for (int i = 0; i < 8; i++) {
            int idx = tid + i * 256;
            int arr = idx >> 9;
            int rem = idx & 511;
            int row = rem >> 2;
            int q   = rem & 3;
            uint32_t saddr = sbase + (uint32_t)(stage * 4 + arr) * TILE_BYTES_G
                           + (uint32_t)row * 80 + q * 16;
            const __nv_bfloat16* g = srcs[arr] + (size_t)row * Kdim + k0 + q * 8;
            CP_ASYNC16(saddr, (const void*)g);
        }
    };

    load_stage(0, 0);
    CP_COMMIT();

    const int fr = lane >> 2;
    const int fq = lane & 3;

    for (int t = 0; t < NT; ++t) {
        const int stage = t & 1;
        if (t + 1 < NT) {
            load_stage(t + 1, stage ^ 1);
            CP_COMMIT();
            CP_WAIT(1);
        } else {
            CP_WAIT(0);
        }
        __syncthreads();

        const uint32_t aH = sbase + (uint32_t)(stage * 4 + 0) * TILE_BYTES_G;
        const uint32_t aL = sbase + (uint32_t)(stage * 4 + 1) * TILE_BYTES_G;
        const uint32_t bH = sbase + (uint32_t)(stage * 4 + 2) * TILE_BYTES_G;
        const uint32_t bL = sbase + (uint32_t)(stage * 4 + 3) * TILE_BYTES_G;

#pragma unroll
        for (int kc = 0; kc < 2; kc++) {
            const int kb = kc * 32 + koff;
            uint32_t ah[4][4], xf[4][4], bx[2][4];
            // Ah fragments (live all 3 passes)
#pragma unroll
            for (int mb = 0; mb < 4; mb++)
                ldsm_x4(ah[mb], aH + (uint32_t)(wm + mb * 16 + arow) * 80 + kb);
            // Bh fragments (live passes 0 and 1)
#pragma unroll
            for (int p = 0; p < 2; p++)
                ldsm_x4(bx[p], bH + (uint32_t)(wn + p * 16 + arow) * 80 + kb);
            // pass 0: Ah * Bh
#pragma unroll
            for (int mb = 0; mb < 4; mb++)
#pragma unroll
                for (int nb = 0; nb < 4; nb++)
                    mma_bf16(acc[mb][nb], ah[mb], bx[nb >> 1][nb & 1], bx[nb >> 1][2 + (nb & 1)]);
            // Al fragments
#pragma unroll
            for (int mb = 0; mb < 4; mb++)
                ldsm_x4(xf[mb], aL + (uint32_t)(wm + mb * 16 + arow) * 80 + kb);
            // pass 1: Al * Bh
#pragma unroll
            for (int mb = 0; mb < 4; mb++)
#pragma unroll
                for (int nb = 0; nb < 4; nb++)
                    mma_bf16(acc[mb][nb], xf[mb], bx[nb >> 1][nb & 1], bx[nb >> 1][2 + (nb & 1)]);
            // Bl fragments (overwrite bx)
#pragma unroll
            for (int p = 0; p < 2; p++)
                ldsm_x4(bx[p], bL + (uint32_t)(wn + p * 16 + arow) * 80 + kb);
            // pass 2: Ah * Bl
#pragma unroll
            for (int mb = 0; mb < 4; mb++)
#pragma unroll
                for (int nb = 0; nb < 4; nb++)
                    mma_bf16(acc[mb][nb], ah[mb], bx[nb >> 1][nb & 1], bx[nb >> 1][2 + (nb & 1)]);
        }
        __syncthreads();
    }

    // Epilogue
#pragma unroll
    for (int mb = 0; mb < 4; mb++) {
#pragma unroll
        for (int nb = 0; nb < 4; nb++) {
            int n = nBase + wn + nb * 8 + 2 * fq;
            float bx = bias[n], by = bias[n + 1];
#pragma unroll
            for (int half = 0; half < 2; half++) {
                int m = mBase + wm + mb * 16 + fr + half * 8;
                float rx = acc[mb][nb][half * 2 + 0] + bx;
                float ry = acc[mb][nb][half * 2 + 1] + by;
                if (MODE == 0) {
                    int sel  = n >> 11;
                    int rem  = n & 2047;
                    int head = rem >> 7;
                    int d    = rem & 127;
                    int b    = m >> 11;
                    int s    = m & 2047;
                    __nv_bfloat16* dh = (sel == 0) ? g_Qh : ((sel == 1) ? g_Kh : g_Vh);
                    __nv_bfloat16* dl = (sel == 0) ? g_Ql : ((sel == 1) ? g_Kl : g_Vl);
                    size_t idx = (size_t)((b * NHEADS + head) * NS + s) * HD + d;
                    uint32_t h, l;
                    pack_hl(rx, ry, h, l);
                    *(uint32_t*)&dh[idx] = h;
                    *(uint32_t*)&dl[idx] = l;
                } else {
                    float2 r; r.x = rx; r.y = ry;
                    *(float2*)&C[(size_t)m * NHID + n] = r;
                }
            }
        }
    }
}

// ---------------------------------------------------------------------------
// Causal flash attention on HMMA, split-bf16 3-pass, ldmatrix fragment loads.
// Grid (16 q-tiles, 32 bh), 256 threads = 8 warps, each warp owns 16 q-rows.
// SMEM u32 layout:
//   Qh:0  Ql:8704  Kh:17408  Kl:21760  Vth:26112  Vtl:30720   (total 141312 B)
//   Q/K tiles: [rows][136 halves] (272 B); Vt: [128 d][36 u32 key-pairs] (144 B)
// ---------------------------------------------------------------------------
#define AQH 0
#define AQL 8704
#define AKH 17408
#define AKL 21760
#define AVH 26112
#define AVL 30720
#define ATTN_SMEM 141312

__global__ __launch_bounds__(256)
void attn_mma()
{
    extern __shared__ char smem[];
    const uint32_t sbase = smem_u32(smem);
    uint32_t* S32 = (uint32_t*)smem;

    const int tid = threadIdx.x;
    const int wid = tid >> 5;
    const int lane = tid & 31;
    const int fr = lane >> 2;
    const int fq = lane & 3;
    const int arow = (lane & 7) + ((lane >> 3) & 1) * 8;
    const int koff = ((lane >> 4) & 1) * 16;
    const int bh = blockIdx.y;
    const int qt = blockIdx.x;
    const int q0 = qt * 128;

    const size_t hoff = (size_t)bh * NS * HD;
    const __nv_bfloat16* Qhg = g_Qh + hoff;
    const __nv_bfloat16* Qlg = g_Ql + hoff;
    const __nv_bfloat16* Khg = g_Kh + hoff;
    const __nv_bfloat16* Klg = g_Kl + hoff;
    const __nv_bfloat16* Vhg = g_Vh + hoff;
    const __nv_bfloat16* Vlg = g_Vl + hoff;

    // load Q tile (128 x 128 halves, hi+lo): 16 chunks/thread
#pragma unroll
    for (int arr = 0; arr < 2; arr++) {
        const __nv_bfloat16* src = arr ? Qlg : Qhg;
        uint32_t dbase = sbase + (arr ? AQL : AQH) * 4;
#pragma unroll
        for (int i = 0; i < 8; i++) {
            int idx = tid + i * 256;
            int row = idx >> 4;
            int c   = idx & 15;
            CP_ASYNC16(dbase + row * 272 + c * 16,
                       (const void*)(src + (size_t)(q0 + row) * HD + c * 8));
        }
    }
    CP_COMMIT();

    float m0 = -1e30f, m1 = -1e30f, l0 = 0.f, l1 = 0.f;
    float o[16][4];
#pragma unroll
    for (int i = 0; i < 16; i++)
#pragma unroll
        for (int j = 0; j < 4; j++) o[i][j] = 0.f;

    const float scl = 0.08838834764831845f;   // 1/sqrt(128)
    const int NTk = 2 * qt + 2;

    for (int jt = 0; jt < NTk; jt++) {
        const int k0 = jt * 64;
        __syncthreads();   // previous tile's consumers done

        // K tile (64 x 128 halves, hi+lo): cp.async, 8 chunks/thread
#pragma unroll
        for (int arr = 0; arr < 2; arr++) {
            const __nv_bfloat16* src = arr ? Klg : Khg;
            uint32_t dbase = sbase + (arr ? AKL : AKH) * 4;
#pragma unroll
            for (int i = 0; i < 4; i++) {
                int idx = tid + i * 256;
                int row = idx >> 4;
                int c   = idx & 15;
                CP_ASYNC16(dbase + row * 272 + c * 16,
                           (const void*)(src + (size_t)(k0 + row) * HD + c * 8));
            }
        }
        CP_COMMIT();

        // V tile -> smem transposed as packed key-pairs: Vt[d][kp] u32
        {
            const int kp  = tid & 31;          // key pair 0..31
            const int dcb = tid >> 5;          // base d-chunk 0..7
#pragma unroll
            for (int arr = 0; arr < 2; arr++) {
                const __nv_bfloat16* src = arr ? Vlg : Vhg;
                const int vb = arr ? AVL : AVH;
#pragma unroll
                for (int ds = 0; ds < 2; ds++) {
                    int dc = dcb + ds * 8;     // d-chunk 0..15
                    uint4 a = *(const uint4*)(src + (size_t)(k0 + 2 * kp) * HD + dc * 8);
                    uint4 b = *(const uint4*)(src + (size_t)(k0 + 2 * kp + 1) * HD + dc * 8);
                    int base = vb + (dc * 8) * 36 + kp;
                    S32[base + 0 * 36] = __byte_perm(a.x, b.x, 0x5410);
                    S32[base + 1 * 36] = __byte_perm(a.x, b.x, 0x7632);
                    S32[base + 2 * 36] = __byte_perm(a.y, b.y, 0x5410);
                    S32[base + 3 * 36] = __byte_perm(a.y, b.y, 0x7632);
                    S32[base + 4 * 36] = __byte_perm(a.z, b.z, 0x5410);
                    S32[base + 5 * 36] = __byte_perm(a.z, b.z, 0x7632);
                    S32[base + 6 * 36] = __byte_perm(a.w, b.w, 0x5410);
                    S32[base + 7 * 36] = __byte_perm(a.w, b.w, 0x7632);
                }
            }
        }
        CP_WAIT(0);
        __syncthreads();

        // skip warps whose entire row range is below this key tile (fully masked)
        if (k0 <= q0 + wid * 16 + 15) {
            // ---- S = Q K^T (3 passes, hoisted ldmatrix loads) ----
            float sacc[8][4];
#pragma unroll
            for (int nb = 0; nb < 8; nb++)
#pragma unroll
                for (int e = 0; e < 4; e++) sacc[nb][e] = 0.f;

            const int r0 = wid * 16 + fr;
            const uint32_t qrow = (uint32_t)(wid * 16 + arow) * 272;
#pragma unroll
            for (int kc = 0; kc < 8; kc++) {
                const int kb = kc * 32 + koff;
                uint32_t qh[4], ql[4], kf[4][4];
                ldsm_x4(qh, sbase + AQH * 4 + qrow + kb);
                ldsm_x4(ql, sbase + AQL * 4 + qrow + kb);
#pragma unroll
                for (int p = 0; p < 4; p++)
                    ldsm_x4(kf[p], sbase + AKH * 4 + (uint32_t)(p * 16 + arow) * 272 + kb);
                // Qh*Kh and Ql*Kh
#pragma unroll
                for (int nb = 0; nb < 8; nb++) {
                    uint32_t b0 = kf[nb >> 1][nb & 1], b1 = kf[nb >> 1][2 + (nb & 1)];
                    mma_bf16(sacc[nb], qh, b0, b1);
                    mma_bf16(sacc[nb], ql, b0, b1);
                }
                // Kl (overwrite kf)
#pragma unroll
                for (int p = 0; p < 4; p++)
                    ldsm_x4(kf[p], sbase + AKL * 4 + (uint32_t)(p * 16 + arow) * 272 + kb);
#pragma unroll
                for (int nb = 0; nb < 8; nb++)
                    mma_bf16(sacc[nb], qh, kf[nb >> 1][nb & 1], kf[nb >> 1][2 + (nb & 1)]);
            }

            // ---- scale + causal mask ----
            const bool need_mask = (jt >= 2 * qt);
            const int gq0 = q0 + r0;
#pragma unroll
            for (int nb = 0; nb < 8; nb++) {
#pragma unroll
                for (int e = 0; e < 4; e++) {
                    float s = sacc[nb][e] * scl;
                    if (need_mask) {
                        int gq = gq0 + ((e >= 2) ? 8 : 0);
                        int gk = k0 + nb * 8 + 2 * fq + (e & 1);
                        if (gk > gq) s = -1e30f;
                    }
                    sacc[nb][e] = s;
                }
            }

            // ---- online softmax (registers + quad shuffles) ----
            float t0 = -1e30f, t1 = -1e30f;
#pragma unroll
            for (int nb = 0; nb < 8; nb++) {
                t0 = fmaxf(t0, fmaxf(sacc[nb][0], sacc[nb][1]));
                t1 = fmaxf(t1, fmaxf(sacc[nb][2], sacc[nb][3]));
            }
            t0 = fmaxf(t0, __shfl_xor_sync(0xffffffffu, t0, 1));
            t0 = fmaxf(t0, __shfl_xor_sync(0xffffffffu, t0, 2));
            t1 = fmaxf(t1, __shfl_xor_sync(0xffffffffu, t1, 1));
            t1 = fmaxf(t1, __shfl_xor_sync(0xffffffffu, t1, 2));
            float mn0 = fmaxf(m0, t0), mn1 = fmaxf(m1, t1);
            float al0 = __expf(m0 - mn0), al1 = __expf(m1 - mn1);
            float s0 = 0.f, s1 = 0.f;
#pragma unroll
            for (int nb = 0; nb < 8; nb++) {
                float p;
                p = __expf(sacc[nb][0] - mn0); sacc[nb][0] = p; s0 += p;
                p = __expf(sacc[nb][1] - mn0); sacc[nb][1] = p; s0 += p;
                p = __expf(sacc[nb][2] - mn1); sacc[nb][2] = p; s1 += p;
                p = __expf(sacc[nb][3] - mn1); sacc[nb][3] = p; s1 += p;
            }
            s0 += __shfl_xor_sync(0xffffffffu, s0, 1);
            s0 += __shfl_xor_sync(0xffffffffu, s0, 2);
            s1 += __shfl_xor_sync(0xffffffffu, s1, 1);
            s1 += __shfl_xor_sync(0xffffffffu, s1, 2);
            l0 = l0 * al0 + s0;  l1 = l1 * al1 + s1;
            m0 = mn0;  m1 = mn1;

            // rescale O
#pragma unroll
            for (int db = 0; db < 16; db++) {
                o[db][0] *= al0; o[db][1] *= al0;
                o[db][2] *= al1; o[db][3] *= al1;
            }

            // ---- pack P as A-fragments (hi/lo), in registers ----
            uint32_t pah[4][4], pal[4][4];
#pragma unroll
            for (int kc2 = 0; kc2 < 4; kc2++) {
                int n0 = 2 * kc2, n1 = n0 + 1;
                pack_hl(sacc[n0][0], sacc[n0][1], pah[kc2][0], pal[kc2][0]);
                pack_hl(sacc[n0][2], sacc[n0][3], pah[kc2][1], pal[kc2][1]);
                pack_hl(sacc[n1][0], sacc[n1][1], pah[kc2][2], pal[kc2][2]);
                pack_hl(sacc[n1][2], sacc[n1][3], pah[kc2][3], pal[kc2][3]);
            }

            // ---- O += P V (3 passes; Vh reused for Ph and Pl) ----
#pragma unroll
            for (int kc2 = 0; kc2 < 4; kc2++) {
                const int kb2 = kc2 * 32 + koff;
#pragma unroll
                for (int p = 0; p < 8; p++) {
                    uint32_t vf[4];
                    uint32_t vrow = (uint32_t)(p * 16 + arow) * 144;
                    ldsm_x4(vf, sbase + AVH * 4 + vrow + kb2);
                    mma_bf16(o[2 * p],     pah[kc2], vf[0], vf[2]);
                    mma_bf16(o[2 * p + 1], pah[kc2], vf[1], vf[3]);
                    mma_bf16(o[2 * p],     pal[kc2], vf[0], vf[2]);
                    mma_bf16(o[2 * p + 1], pal[kc2], vf[1], vf[3]);
                    ldsm_x4(vf, sbase + AVL * 4 + vrow + kb2);
                    mma_bf16(o[2 * p],     pah[kc2], vf[0], vf[2]);
                    mma_bf16(o[2 * p + 1], pah[kc2], vf[1], vf[3]);
                }
            }
        }
    }

    // ---- epilogue: O/l -> g_Oh/g_Ol (hi/lo bf16, row-major [M][2048]) ----
    const int b    = bh >> 4;
    const int head = bh & 15;
    const int row0 = b * NS + q0 + wid * 16 + fr;
    const int col0 = head * HD + 2 * fq;
    const float li0 = 1.f / l0, li1 = 1.f / l1;
#pragma unroll
    for (int db = 0; db < 16; db++) {
        uint32_t h, l;
        size_t i0 = (size_t)row0 * NHID + col0 + db * 8;
        pack_hl(o[db][0] * li0, o[db][1] * li0, h, l);
        *(uint32_t*)&g_Oh[i0] = h;
        *(uint32_t*)&g_Ol[i0] = l;
        size_t i1 = i0 + (size_t)8 * NHID;
        pack_hl(o[db][2] * li1, o[db][3] * li1, h, l);
        *(uint32_t*)&g_Oh[i1] = h;
        *(uint32_t*)&g_Ol[i1] = l;
    }
}

// ---------------------------------------------------------------------------
extern "C" void kernel_launch(void* const* d_in, const int* in_sizes, int n_in,
                              void* d_out, int out_size)
{
    const float* x    = (const float*)d_in[0];
    const float* Wqkv = (const float*)d_in[1];
    const float* bqkv = (const float*)d_in[2];
    const float* Wo   = (const float*)d_in[3];
    const float* bo   = (const float*)d_in[4];
    float* out = (float*)d_out;

    cudaFuncSetAttribute(attn_mma, cudaFuncAttributeMaxDynamicSharedMemorySize,
                         (int)ATTN_SMEM);
    cudaFuncSetAttribute(gemm_mma<0>, cudaFuncAttributeMaxDynamicSharedMemorySize,
                         (int)GEMM_SMEM);
    cudaFuncSetAttribute(gemm_mma<1>, cudaFuncAttributeMaxDynamicSharedMemorySize,
                         (int)GEMM_SMEM);

    // hi/lo splits (+ weight transposes to [N][K] K-major)
    split_x_kernel<<<(M_TOT * NHID) / 1024, 256>>>(x);
    split_tr_kernel<0><<<dim3(N3 / 32, NHID / 32), dim3(32, 8)>>>(Wqkv);
    split_tr_kernel<1><<<dim3(NHID / 32, NHID / 32), dim3(32, 8)>>>(Wo);

    // 1) QKV projection (HMMA), writes Q/K/V hi/lo bf16 per head
    gemm_mma<0><<<dim3(N3 / 128, M_TOT / 128), 256, GEMM_SMEM>>>(bqkv, nullptr);

    // 2) causal attention (HMMA), writes O hi/lo bf16
    attn_mma<<<dim3(NS / 128, NB * NHEADS), 256, ATTN_SMEM>>>();

    // 3) output projection (HMMA)
    gemm_mma<1><<<dim3(NHID / 128, M_TOT / 128), 256, GEMM_SMEM>>>(bo, out);
}